// round 17
// baseline (speedup 1.0000x reference)
#include <cuda_runtime.h>
#include <math.h>

#define NN   50000
#define EE   800000
#define FIN  32
#define HH   64
#define H2   128
#define EDIM 16
#define GG   64
#define COUT 40
#define PCHUNK 64
#define HIST_BLKS 782
#define LIN_BLKS 782        // 64-node tiles
#define SCAN_BLKS 49

typedef unsigned long long u64;
typedef unsigned int u32;

#define FMA2(acc, a, b) asm("fma.rn.f32x2 %0, %1, %2, %0;" : "+l"(acc) : "l"(a), "l"(b))
#define PACK2(d, lo, hi) asm("mov.b64 %0, {%1, %2};" : "=l"(d) : "r"(lo), "r"(hi))
#define UNPACK2(lo, hi, s) asm("mov.b64 {%0, %1}, %2;" : "=r"(lo), "=r"(hi) : "l"(s))

// ---------------- scratch (no allocation allowed) ----------------
// All mutable state is returned to zero/overwritten every call.
__device__ float g_h[NN * HH];      // node features (residual stream)
__device__ float g_num[NN * HH];    // softmax numerator accumulator
__device__ float g_den[NN * HH];    // softmax denominator accumulator
__device__ float g_hmid[NN * H2];   // MLP hidden
__device__ float g_sA[3][HH];
__device__ float g_qA[3][HH];
__device__ float g_sB[2][H2];
__device__ float g_qB[2][H2];
__device__ float g_pool[GG * HH];
__device__ float g_cnt[GG];
// CSR scratch
__device__ int g_deg[NN];
__device__ int g_cur[NN];           // seeded with offsets by k_scan
__device__ int g_off[NN + 1];
__device__ int g_psrc[EE];
__device__ int g_pdst[EE];
__device__ float g_eac[(size_t)EE * EDIM];   // edge_attr in CSR order
__device__ u64 g_look[64];

// -------- merged: degree histogram (blocks [0,782)) + input linear ---------
__global__ void k_histlin(const int* __restrict__ ei,
                          const float* __restrict__ x,
                          const float* __restrict__ W,
                          const float* __restrict__ b) {
    __shared__ float xs[FIN * 68];        // transposed [k][node], pad 68
    __shared__ float sred[16][HH];        // 4KB
    int tid = threadIdx.x;

    if (blockIdx.x < HIST_BLKS) {         // ---- histogram part ----
        int t = blockIdx.x * 256 + tid;
        if (t * 4 < EE) {
            int4 d4 = ((const int4*)(ei + EE))[t];
            atomicAdd(&g_deg[d4.x], 1);
            atomicAdd(&g_deg[d4.y], 1);
            atomicAdd(&g_deg[d4.z], 1);
            atomicAdd(&g_deg[d4.w], 1);
        }
        return;
    }
    // ---- input linear: 64-node tile, f32x2 ----
    int bid = blockIdx.x - HIST_BLKS;
    int n0 = bid * 64;
    for (int idx = tid; idx < 64 * 8; idx += 256) {
        int r = idx >> 3, q = idx & 7;
        int gn = n0 + r;
        float4 v = (gn < NN) ? ((const float4*)(x + (size_t)gn * FIN))[q]
                             : make_float4(0.f, 0.f, 0.f, 0.f);
        xs[(q * 4 + 0) * 68 + r] = v.x;
        xs[(q * 4 + 1) * 68 + r] = v.y;
        xs[(q * 4 + 2) * 68 + r] = v.z;
        xs[(q * 4 + 3) * 68 + r] = v.w;
    }
    __syncthreads();
    int tx = tid & 15, ty = tid >> 4;
    int col = tx * 4, row0 = ty * 4;
    u64 acc[2][4];
#pragma unroll
    for (int p = 0; p < 2; p++)
#pragma unroll
        for (int c = 0; c < 4; c++) acc[p][c] = 0ull;
#pragma unroll 4
    for (int k = 0; k < FIN; k++) {
        ulonglong2 ap = *(const ulonglong2*)&xs[k * 68 + row0];
        float4 wv = *(const float4*)&W[k * HH + col];
#pragma unroll
        for (int c = 0; c < 4; c++) {
            u32 wb = __float_as_uint(((const float*)&wv)[c]);
            u64 wd; PACK2(wd, wb, wb);
            FMA2(acc[0][c], ap.x, wd);
            FMA2(acc[1][c], ap.y, wd);
        }
    }
    float4 bb = *(const float4*)&b[col];
    float s[4] = {0.f, 0.f, 0.f, 0.f}, q[4] = {0.f, 0.f, 0.f, 0.f};
#pragma unroll
    for (int p = 0; p < 2; p++) {
        float o0[4], o1[4];
#pragma unroll
        for (int c = 0; c < 4; c++) {
            u32 l_, h_; UNPACK2(l_, h_, acc[p][c]);
            o0[c] = __uint_as_float(l_) + ((const float*)&bb)[c];
            o1[c] = __uint_as_float(h_) + ((const float*)&bb)[c];
        }
        int na = n0 + row0 + p * 2;
        if (na < NN) {
            *(float4*)&g_h[na * HH + col] = make_float4(o0[0], o0[1], o0[2], o0[3]);
#pragma unroll
            for (int c = 0; c < 4; c++) { s[c] += o0[c]; q[c] += o0[c] * o0[c]; }
        }
        if (na + 1 < NN) {
            *(float4*)&g_h[(na + 1) * HH + col] = make_float4(o1[0], o1[1], o1[2], o1[3]);
#pragma unroll
            for (int c = 0; c < 4; c++) { s[c] += o1[c]; q[c] += o1[c] * o1[c]; }
        }
    }
#pragma unroll
    for (int c = 0; c < 4; c++) sred[ty][col + c] = s[c];
    __syncthreads();
    if (tid < HH) {
        float S = 0.f;
#pragma unroll
        for (int i = 0; i < 16; i++) S += sred[i][tid];
        atomicAdd(&g_sA[0][tid], S);
    }
    __syncthreads();
#pragma unroll
    for (int c = 0; c < 4; c++) sred[ty][col + c] = q[c];
    __syncthreads();
    if (tid < HH) {
        float Q = 0.f;
#pragma unroll
        for (int i = 0; i < 16; i++) Q += sred[i][tid];
        atomicAdd(&g_qA[0][tid], Q);
    }
}

// scan with decoupled lookback; seeds g_cur; also zeroes num/den for layer 0
__global__ void k_scan() {
    __shared__ int sh[1024];
    __shared__ int exc_sh;
    int b = blockIdx.x, t = threadIdx.x;
    int i = b * 1024 + t;
    int v = (i < NN) ? g_deg[i] : 0;
    sh[t] = v;
    __syncthreads();
    for (int off = 1; off < 1024; off <<= 1) {
        int u = (t >= off) ? sh[t - off] : 0;
        __syncthreads();
        sh[t] += u;
        __syncthreads();
    }
    int total = sh[1023];
    if (t == 0) {
        const u64 FA = 1ull << 62, FP = 2ull << 62;
        if (b == 0) {
            atomicExch(&g_look[0], FP | (u32)total);
            exc_sh = 0;
        } else {
            atomicExch(&g_look[b], FA | (u32)total);
            int run = 0, j = b - 1;
            while (1) {
                u64 s = atomicAdd(&g_look[j], 0ull);
                u64 f = s >> 62;
                if (f == 0) continue;
                int val = (int)(s & 0xFFFFFFFFull);
                run += val;
                if (f == 2) break;
                j--;
            }
            atomicExch(&g_look[b], FP | (u32)(run + total));
            exc_sh = run;
        }
    }
    __syncthreads();
    int e = exc_sh;
    if (i < NN) {
        int off = e + sh[t] - v;   // exclusive
        g_off[i] = off;
        g_cur[i] = off;            // seed for bump allocation in k_scatter
    }
    if (b == 0 && t == 0) g_off[NN] = EE;
    // zero num/den for layer 0 (float4 grid-stride)
    float4 z4 = make_float4(0.f, 0.f, 0.f, 0.f);
    for (int i4 = b * 1024 + t; i4 < NN * HH / 4; i4 += SCAN_BLKS * 1024) {
        ((float4*)g_num)[i4] = z4;
        ((float4*)g_den)[i4] = z4;
    }
}

// scatter: CSR src/dst lists + edge_attr copied into CSR order
__global__ void k_scatter(const int* __restrict__ ei, const float* __restrict__ ea) {
    int e = blockIdx.x * blockDim.x + threadIdx.x;
    if (e >= EE) return;
    int src = __ldg(&ei[e]);
    int d = __ldg(&ei[EE + e]);
    int idx = atomicAdd(&g_cur[d], 1);
    g_psrc[idx] = src;
    g_pdst[idx] = d;
    const float4* sp = (const float4*)(ea + (size_t)e * EDIM);
    float4 v0 = sp[0], v1 = sp[1], v2 = sp[2], v3 = sp[3];
    float4* dp = (float4*)(g_eac + (size_t)idx * EDIM);
    dp[0] = v0; dp[1] = v1; dp[2] = v2; dp[3] = v3;
}

// ------- fused edge kernel (CSR order): edge-MLP + BN(h[src]) + softmax ----
// 64 slots/block, 256 thr; thread = (tx: col quartet, ty: 4 consecutive slots)
// segmented run-accumulation over equal-dst runs; atomic flush at run ends
__global__ void k_edgefused(const float* __restrict__ W, const float* __restrict__ bias,
                            const float* __restrict__ gamma, const float* __restrict__ beta,
                            const float* __restrict__ tptr, int l) {
    __shared__ float As[16 * 68];       // transposed [k][slot], pad 68
    __shared__ int ssrc[64], sdst[64];
    int tid = threadIdx.x;  // 256
    int e0 = blockIdx.x * 64;
    if (tid < 64) {
        ssrc[tid] = g_psrc[e0 + tid];
        sdst[tid] = g_pdst[e0 + tid];
    }
    {
        int r = tid >> 2, q = tid & 3;  // 64 slots x 4 quarters
        float4 v = ((const float4*)(g_eac + (size_t)(e0 + r) * EDIM))[q];
        As[(q * 4 + 0) * 68 + r] = v.x;
        As[(q * 4 + 1) * 68 + r] = v.y;
        As[(q * 4 + 2) * 68 + r] = v.z;
        As[(q * 4 + 3) * 68 + r] = v.w;
    }
    __syncthreads();
    int tx = tid & 15, ty = tid >> 4;
    int col = tx * 4, s0 = ty * 4;
    // BN constants for cols col..col+3
    float4 sA4 = *(const float4*)&g_sA[l][col];
    float4 qA4 = *(const float4*)&g_qA[l][col];
    float4 gm4 = *(const float4*)&gamma[col];
    float4 bt4 = *(const float4*)&beta[col];
    float sc[4], sf[4];
#pragma unroll
    for (int c = 0; c < 4; c++) {
        float mu = ((const float*)&sA4)[c] * (1.f / NN);
        float var = ((const float*)&qA4)[c] * (1.f / NN) - mu * mu;
        float s = ((const float*)&gm4)[c] * rsqrtf(var + 1e-5f);
        sc[c] = s;
        sf[c] = ((const float*)&bt4)[c] - mu * s;
    }
    float tc2 = tptr[0] * 1.4426950408889634f;
    // edge-MLP k-loop (f32x2, slot pairs)
    u64 acc[2][4];
#pragma unroll
    for (int p = 0; p < 2; p++)
#pragma unroll
        for (int c = 0; c < 4; c++) acc[p][c] = 0ull;
#pragma unroll
    for (int k = 0; k < EDIM; k++) {
        ulonglong2 ap = *(const ulonglong2*)&As[k * 68 + s0];
        float4 wv = *(const float4*)&W[k * HH + col];
#pragma unroll
        for (int c = 0; c < 4; c++) {
            u32 wb = __float_as_uint(((const float*)&wv)[c]);
            u64 wd; PACK2(wd, wb, wb);
            FMA2(acc[0][c], ap.x, wd);
            FMA2(acc[1][c], ap.y, wd);
        }
    }
    float4 bbv = *(const float4*)&bias[col];
    float emb[4][4];
#pragma unroll
    for (int pp = 0; pp < 2; pp++)
#pragma unroll
        for (int c = 0; c < 4; c++) {
            u32 lo, hi; UNPACK2(lo, hi, acc[pp][c]);
            emb[pp * 2][c]     = __uint_as_float(lo) + ((const float*)&bbv)[c];
            emb[pp * 2 + 1][c] = __uint_as_float(hi) + ((const float*)&bbv)[c];
        }
    // segmented accumulate over 4 consecutive slots
    float dacc[4] = {0.f, 0.f, 0.f, 0.f}, nacc[4] = {0.f, 0.f, 0.f, 0.f};
    int prev = sdst[s0];
#pragma unroll
    for (int p = 0; p < 4; p++) {
        int s = s0 + p;
        int dst = sdst[s];
        if (dst != prev) {
            int base = prev * HH + col;
#pragma unroll
            for (int c = 0; c < 4; c++) {
                atomicAdd(&g_den[base + c], dacc[c]);
                atomicAdd(&g_num[base + c], nacc[c]);
                dacc[c] = 0.f; nacc[c] = 0.f;
            }
            prev = dst;
        }
        float4 hv = *(const float4*)&g_h[(size_t)ssrc[s] * HH + col];
        float hvv[4] = {hv.x, hv.y, hv.z, hv.w};
#pragma unroll
        for (int c = 0; c < 4; c++) {
            float z = fmaxf(hvv[c] * sc[c] + sf[c], 0.f);
            float m = fmaxf(z + emb[p][c], 0.f) + 1e-7f;
            float ex = exp2f(m * tc2);   // no max-shift: m in [1e-7, ~6]
            dacc[c] += ex;
            nacc[c] += ex * m;
        }
    }
    {
        int base = prev * HH + col;
#pragma unroll
        for (int c = 0; c < 4; c++) {
            atomicAdd(&g_den[base + c], dacc[c]);
            atomicAdd(&g_num[base + c], nacc[c]);
        }
    }
}

// ------- MLP1 GEMM: stages agg = num/(den+eps) + relu(BN(h)) inline --------
__global__ void k_mlp1(const float* __restrict__ w1, const float* __restrict__ b1,
                       const float* __restrict__ gamma, const float* __restrict__ beta,
                       int l) {
    __shared__ float As[64 * 66];       // transposed [k][n]
    __shared__ float sred[8][H2];
    __shared__ float scs[HH], sfs[HH];
    int tid = threadIdx.x;  // 256
    int n0 = blockIdx.x * 64;
    if (tid < HH) {
        float mu = g_sA[l][tid] * (1.f / NN);
        float var = g_qA[l][tid] * (1.f / NN) - mu * mu;
        float s = gamma[tid] * rsqrtf(var + 1e-5f);
        scs[tid] = s;
        sfs[tid] = beta[tid] - mu * s;
    }
    __syncthreads();
    for (int idx = tid; idx < 64 * 16; idx += 256) {
        int r = idx >> 4, c4 = (idx & 15) * 4;
        int gn = n0 + r;
        float a[4] = {0.f, 0.f, 0.f, 0.f};
        if (gn < NN) {
            float4 nm = *(const float4*)&g_num[gn * HH + c4];
            float4 dn = *(const float4*)&g_den[gn * HH + c4];
            float4 hv = *(const float4*)&g_h[gn * HH + c4];
            float nmv[4] = {nm.x, nm.y, nm.z, nm.w};
            float dnv[4] = {dn.x, dn.y, dn.z, dn.w};
            float hvv[4] = {hv.x, hv.y, hv.z, hv.w};
#pragma unroll
            for (int c = 0; c < 4; c++) {
                float z = fmaxf(hvv[c] * scs[c4 + c] + sfs[c4 + c], 0.f);
                a[c] = nmv[c] / (dnv[c] + 1e-16f) + z;
            }
        }
        As[(c4 + 0) * 66 + r] = a[0];
        As[(c4 + 1) * 66 + r] = a[1];
        As[(c4 + 2) * 66 + r] = a[2];
        As[(c4 + 3) * 66 + r] = a[3];
    }
    __syncthreads();
    int tx = tid & 31, ty = tid >> 5;
    int col = tx * 4, row0 = ty * 8;
    u64 acc[4][4];
#pragma unroll
    for (int rp = 0; rp < 4; rp++)
#pragma unroll
        for (int c = 0; c < 4; c++) acc[rp][c] = 0ull;
#pragma unroll 4
    for (int k = 0; k < 64; k++) {
        u64 ap[4];
#pragma unroll
        for (int rp = 0; rp < 4; rp++)
            ap[rp] = *(const u64*)&As[k * 66 + row0 + rp * 2];
        float4 wv = *(const float4*)&w1[k * H2 + col];
#pragma unroll
        for (int c = 0; c < 4; c++) {
            u32 wb = __float_as_uint(((const float*)&wv)[c]);
            u64 wd; PACK2(wd, wb, wb);
#pragma unroll
            for (int rp = 0; rp < 4; rp++) FMA2(acc[rp][c], ap[rp], wd);
        }
    }
    float4 bb = *(const float4*)&b1[col];
    float s[4] = {0.f, 0.f, 0.f, 0.f}, q[4] = {0.f, 0.f, 0.f, 0.f};
#pragma unroll
    for (int rp = 0; rp < 4; rp++) {
        float o0[4], o1[4];
#pragma unroll
        for (int c = 0; c < 4; c++) {
            u32 lo, hi; UNPACK2(lo, hi, acc[rp][c]);
            o0[c] = __uint_as_float(lo) + ((const float*)&bb)[c];
            o1[c] = __uint_as_float(hi) + ((const float*)&bb)[c];
        }
        int na = n0 + row0 + rp * 2;
        if (na < NN) {
            *(float4*)&g_hmid[na * H2 + col] = make_float4(o0[0], o0[1], o0[2], o0[3]);
#pragma unroll
            for (int c = 0; c < 4; c++) { s[c] += o0[c]; q[c] += o0[c] * o0[c]; }
        }
        if (na + 1 < NN) {
            *(float4*)&g_hmid[(na + 1) * H2 + col] = make_float4(o1[0], o1[1], o1[2], o1[3]);
#pragma unroll
            for (int c = 0; c < 4; c++) { s[c] += o1[c]; q[c] += o1[c] * o1[c]; }
        }
    }
#pragma unroll
    for (int c = 0; c < 4; c++) sred[ty][col + c] = s[c];
    __syncthreads();
    if (tid < H2) {
        float S = 0.f;
#pragma unroll
        for (int i = 0; i < 8; i++) S += sred[i][tid];
        atomicAdd(&g_sB[l][tid], S);
    }
    __syncthreads();
#pragma unroll
    for (int c = 0; c < 4; c++) sred[ty][col + c] = q[c];
    __syncthreads();
    if (tid < H2) {
        float Q = 0.f;
#pragma unroll
        for (int i = 0; i < 8; i++) Q += sred[i][tid];
        atomicAdd(&g_qB[l][tid], Q);
    }
}

// ------- MLP2 GEMM (128 thr), fused BN2+ReLU staging + residual ------------
// l==0: also zeroes num/den for this block's nodes (consumed by mlp1 already)
__global__ void k_mlp2(const float* __restrict__ w2, const float* __restrict__ b2,
                       const float* __restrict__ gamma, const float* __restrict__ beta,
                       int l) {
    __shared__ float As[H2 * 66];       // transposed [k][n]
    __shared__ float scs[H2], sfs[H2];
    __shared__ float sred[8][HH];
    int tid = threadIdx.x;  // 128
    int n0 = blockIdx.x * 64;
    if (l == 0) {   // zero num/den for next layer
        float4 z4 = make_float4(0.f, 0.f, 0.f, 0.f);
        for (int i4 = tid; i4 < 64 * HH / 4; i4 += 128) {
            int n = n0 + (i4 >> 4);
            if (n < NN) {
                ((float4*)(g_num + (size_t)n0 * HH))[i4] = z4;
                ((float4*)(g_den + (size_t)n0 * HH))[i4] = z4;
            }
        }
    }
    {   // tid == k
        float mu = g_sB[l][tid] * (1.f / NN);
        float var = g_qB[l][tid] * (1.f / NN) - mu * mu;
        float scr = gamma[tid] * rsqrtf(var + 1e-5f);
        scs[tid] = scr;
        sfs[tid] = beta[tid] - mu * scr;
    }
    __syncthreads();
    for (int idx = tid; idx < 64 * 32; idx += 128) {
        int r = idx >> 5, c4 = (idx & 31) * 4;
        int gn = n0 + r;
        float4 v = (gn < NN) ? *(const float4*)&g_hmid[gn * H2 + c4]
                             : make_float4(0.f, 0.f, 0.f, 0.f);
        As[(c4 + 0) * 66 + r] = fmaxf(v.x * scs[c4]     + sfs[c4],     0.f);
        As[(c4 + 1) * 66 + r] = fmaxf(v.y * scs[c4 + 1] + sfs[c4 + 1], 0.f);
        As[(c4 + 2) * 66 + r] = fmaxf(v.z * scs[c4 + 2] + sfs[c4 + 2], 0.f);
        As[(c4 + 3) * 66 + r] = fmaxf(v.w * scs[c4 + 3] + sfs[c4 + 3], 0.f);
    }
    __syncthreads();
    int tx = tid & 15, ty = tid >> 4;
    int col = tx * 4, row0 = ty * 8;
    u64 acc[4][4];
#pragma unroll
    for (int rp = 0; rp < 4; rp++)
#pragma unroll
        for (int c = 0; c < 4; c++) acc[rp][c] = 0ull;
#pragma unroll 4
    for (int k = 0; k < H2; k++) {
        u64 ap[4];
#pragma unroll
        for (int rp = 0; rp < 4; rp++)
            ap[rp] = *(const u64*)&As[k * 66 + row0 + rp * 2];
        float4 wv = *(const float4*)&w2[k * HH + col];
#pragma unroll
        for (int c = 0; c < 4; c++) {
            u32 wb = __float_as_uint(((const float*)&wv)[c]);
            u64 wd; PACK2(wd, wb, wb);
#pragma unroll
            for (int rp = 0; rp < 4; rp++) FMA2(acc[rp][c], ap[rp], wd);
        }
    }
    float4 bb = *(const float4*)&b2[col];
    float s[4] = {0.f, 0.f, 0.f, 0.f}, q[4] = {0.f, 0.f, 0.f, 0.f};
#pragma unroll
    for (int rp = 0; rp < 4; rp++) {
        float o0[4], o1[4];
#pragma unroll
        for (int c = 0; c < 4; c++) {
            u32 lo, hi; UNPACK2(lo, hi, acc[rp][c]);
            o0[c] = __uint_as_float(lo) + ((const float*)&bb)[c];
            o1[c] = __uint_as_float(hi) + ((const float*)&bb)[c];
        }
        int na = n0 + row0 + rp * 2;
        if (na < NN) {
            float4 h = *(const float4*)&g_h[na * HH + col];
            h.x += o0[0]; h.y += o0[1]; h.z += o0[2]; h.w += o0[3];
            *(float4*)&g_h[na * HH + col] = h;
            s[0] += h.x; s[1] += h.y; s[2] += h.z; s[3] += h.w;
            q[0] += h.x * h.x; q[1] += h.y * h.y; q[2] += h.z * h.z; q[3] += h.w * h.w;
        }
        if (na + 1 < NN) {
            float4 h = *(const float4*)&g_h[(na + 1) * HH + col];
            h.x += o1[0]; h.y += o1[1]; h.z += o1[2]; h.w += o1[3];
            *(float4*)&g_h[(na + 1) * HH + col] = h;
            s[0] += h.x; s[1] += h.y; s[2] += h.z; s[3] += h.w;
            q[0] += h.x * h.x; q[1] += h.y * h.y; q[2] += h.z * h.z; q[3] += h.w * h.w;
        }
    }
#pragma unroll
    for (int c = 0; c < 4; c++) sred[ty][col + c] = s[c];
    __syncthreads();
    if (tid < HH) {
        float S = 0.f;
#pragma unroll
        for (int i = 0; i < 8; i++) S += sred[i][tid];
        atomicAdd(&g_sA[l + 1][tid], S);
    }
    __syncthreads();
#pragma unroll
    for (int c = 0; c < 4; c++) sred[ty][col + c] = q[c];
    __syncthreads();
    if (tid < HH) {
        float Q = 0.f;
#pragma unroll
        for (int i = 0; i < 8; i++) Q += sred[i][tid];
        atomicAdd(&g_qA[l + 1][tid], Q);
    }
}

// ------- global mean pool + g_deg cleanup for next call -------
__global__ void k_pool(const int* __restrict__ batch) {
    int j = threadIdx.x;  // 64
    int zi = blockIdx.x * 64 + j;
    if (zi < NN) g_deg[zi] = 0;          // reset for next call
    int n0 = blockIdx.x * PCHUNK;
    if (n0 >= NN) return;
    int n1 = min(n0 + PCHUNK, NN);
    int cur = batch[n0];
    float s = 0.f, cnt = 0.f;
    for (int n = n0; n < n1; n++) {
        int b = batch[n];
        if (b != cur) {
            atomicAdd(&g_pool[cur * HH + j], s);
            if (j == 0) atomicAdd(&g_cnt[cur], cnt);
            s = 0.f; cnt = 0.f; cur = b;
        }
        s += g_h[n * HH + j];
        cnt += 1.f;
    }
    atomicAdd(&g_pool[cur * HH + j], s);
    if (j == 0) atomicAdd(&g_cnt[cur], cnt);
}

// ------- output + full accumulator cleanup for next call -------
__global__ void k_final(const float* __restrict__ W, const float* __restrict__ b,
                        float* __restrict__ out) {
    __shared__ float p[HH];
    int g = blockIdx.x, tid = threadIdx.x;  // 64 blocks x 64 threads
    float c = fmaxf(g_cnt[g], 1.f);
    p[tid] = fmaxf(g_pool[g * HH + tid] / c, 0.f);
    __syncthreads();
    // cleanup for next call (after reads)
    g_pool[g * HH + tid] = 0.f;
    if (tid == 0) { g_cnt[g] = 0.f; g_look[g] = 0ull; }
    int gi = g * 64 + tid;               // 0..4095
    if (gi < 3 * HH) { ((float*)g_sA)[gi] = 0.f; ((float*)g_qA)[gi] = 0.f; }
    if (gi < 2 * H2) { ((float*)g_sB)[gi] = 0.f; ((float*)g_qB)[gi] = 0.f; }
    if (tid < COUT) {
        float acc = b[tid];
#pragma unroll
        for (int k = 0; k < HH; k++) acc += p[k] * W[k * COUT + tid];
        out[g * COUT + tid] = acc;
    }
}

extern "C" void kernel_launch(void* const* d_in, const int* in_sizes, int n_in,
                              void* d_out, int out_size) {
    const float* x        = (const float*)d_in[0];
    const int*   ei       = (const int*)d_in[1];
    const float* ea       = (const float*)d_in[2];
    const int*   batch    = (const int*)d_in[3];
    const float* lin_in_w = (const float*)d_in[4];
    const float* lin_in_b = (const float*)d_in[5];
    const float* ng       = (const float*)d_in[6];
    const float* nb       = (const float*)d_in[7];
    const float* ew       = (const float*)d_in[8];
    const float* eb       = (const float*)d_in[9];
    const float* tt       = (const float*)d_in[10];
    const float* w1       = (const float*)d_in[11];
    const float* b1       = (const float*)d_in[12];
    const float* mg       = (const float*)d_in[13];
    const float* mb       = (const float*)d_in[14];
    const float* w2       = (const float*)d_in[15];
    const float* b2       = (const float*)d_in[16];
    const float* ow       = (const float*)d_in[17];
    const float* ob       = (const float*)d_in[18];
    float* out = (float*)d_out;

    k_histlin<<<HIST_BLKS + LIN_BLKS, 256>>>(ei, x, lin_in_w, lin_in_b);
    k_scan<<<SCAN_BLKS, 1024>>>();
    k_scatter<<<(EE + 255) / 256, 256>>>(ei, ea);
    for (int l = 0; l < 2; l++) {
        k_edgefused<<<EE / 64, 256>>>(ew + l * EDIM * HH, eb + l * HH,
                                      ng + l * HH, nb + l * HH, tt + l, l);
        k_mlp1<<<(NN + 63) / 64, 256>>>(w1 + l * HH * H2, b1 + l * H2,
                                        ng + l * HH, nb + l * HH, l);
        k_mlp2<<<(NN + 63) / 64, 128>>>(w2 + l * H2 * HH, b2 + l * HH,
                                        mg + l * H2, mb + l * H2, l);
    }
    k_pool<<<(NN + PCHUNK - 1) / PCHUNK, 64>>>(batch);
    k_final<<<GG, 64>>>(ow, ob, out);
}